// round 6
// baseline (speedup 1.0000x reference)
#include <cuda_runtime.h>

#define N_QUBITS 10
#define TPB 64

// Closed-form evaluation of the 10-qubit staircase circuit:
//   E_0 = cos(x_0 + r_0)
//   E_i = cos(x_i + r_i) * (1 - k_{i-1} * (1 - E_{i-1})),  k_j = (1 - cos e_j)/2
// (R0 derivation: each entangling gate is diagonal in its control qubit's Z
// basis; only the diagonal of the 2x2 reduced density matrix propagates.)
//
// One sample per thread: 10 floats = 5 aligned float2 (byte offset 40*t).
// No shared memory, no barriers, no guard (grid exactly covers 16384 samples).
// 256 CTAs x 64 threads: >=1 CTA on every one of 148 SMs, minimal per-SM tail.
__global__ void __launch_bounds__(TPB, 1)
qsa_closed_form_kernel(const float2* __restrict__ inputs2,
                       const float* __restrict__ rot,
                       const float* __restrict__ ent,
                       float2* __restrict__ out2) {
    const int t = blockIdx.x * TPB + threadIdx.x;   // sample index, exact fit

    // 5 independent LDG.64 (MLP = 5), issued first.
    float2 v[5];
    const float2* src = inputs2 + t * 5;
    #pragma unroll
    for (int i = 0; i < 5; i++) v[i] = src[i];

    // Uniform broadcast loads of the tiny parameter vectors.
    float r[N_QUBITS], k[N_QUBITS - 1];
    #pragma unroll
    for (int i = 0; i < N_QUBITS; i++) r[i] = __ldg(&rot[i]);
    #pragma unroll
    for (int i = 0; i < N_QUBITS - 1; i++)
        k[i] = 0.5f - 0.5f * __cosf(__ldg(&ent[i]));   // sin^2(e/2)

    float x[N_QUBITS];
    #pragma unroll
    for (int i = 0; i < 5; i++) { x[2*i] = v[i].x; x[2*i+1] = v[i].y; }

    // All 10 cos are independent (pipelined MUFU); carry chain is 2 FMA/step.
    float c[N_QUBITS];
    #pragma unroll
    for (int i = 0; i < N_QUBITS; i++) c[i] = __cosf(x[i] + r[i]);

    float e[N_QUBITS];
    float carry = 1.0f;
    #pragma unroll
    for (int i = 0; i < N_QUBITS; i++) {
        float ev = c[i] * carry;
        e[i] = ev;
        if (i < N_QUBITS - 1) carry = 1.0f - k[i] * (1.0f - ev);
    }

    float2* dst = out2 + t * 5;
    #pragma unroll
    for (int i = 0; i < 5; i++) {
        float2 o; o.x = e[2*i]; o.y = e[2*i+1];
        dst[i] = o;
    }
}

extern "C" void kernel_launch(void* const* d_in, const int* in_sizes, int n_in,
                              void* d_out, int out_size) {
    const float* inputs = (const float*)d_in[0];  // (16, 1024, 10) fp32
    const float* rot    = (const float*)d_in[1];  // (10,)
    const float* ent    = (const float*)d_in[2];  // (9,)
    float* out = (float*)d_out;

    int total_elems = in_sizes[0];                 // 163840
    int T = total_elems / N_QUBITS;                // 16384 samples
    int blocks = T / TPB;                          // 256, exact

    qsa_closed_form_kernel<<<blocks, TPB>>>(
        reinterpret_cast<const float2*>(inputs), rot, ent,
        reinterpret_cast<float2*>(out));
}

// round 7
// speedup vs baseline: 1.0048x; 1.0048x over previous
#include <cuda_runtime.h>

#define N_QUBITS 10
#define TPB 128

// Closed-form evaluation of the 10-qubit staircase circuit:
//   E_0 = cos(x_0 + r_0)
//   E_i = cos(x_i + r_i) * (1 - k_{i-1} * (1 - E_{i-1})),  k_j = (1 - cos e_j)/2
// (R0 derivation: each entangling gate is diagonal in its control qubit's Z
// basis, so <Z_i> is fixed after gate (i-1,i); with single-qubit states
// (cos, -i sin) only the diagonal of the 2x2 reduced density matrix
// propagates, collapsing the 2^10 state vector to a 10-step scalar recurrence.)
//
// One sample per thread: 10 floats = 5 aligned float2 (byte offset 40*t).
// No shared memory, no barriers, no guard (grid exactly covers 16384 samples).
// 128 CTAs x 128 threads: single wave, best measured wall (6.624us) — the
// kernel sits on the graph-replay/launch floor (timer-tick-identical wall
// across 1.5us of profiled kernel-time variation in R4-R6).
__global__ void __launch_bounds__(TPB, 1)
qsa_closed_form_kernel(const float2* __restrict__ inputs2,
                       const float* __restrict__ rot,
                       const float* __restrict__ ent,
                       float2* __restrict__ out2) {
    const int t = blockIdx.x * TPB + threadIdx.x;   // sample index, exact fit

    // 5 independent LDG.64 (MLP = 5), issued first.
    float2 v[5];
    const float2* src = inputs2 + t * 5;
    #pragma unroll
    for (int i = 0; i < 5; i++) v[i] = src[i];

    // Uniform broadcast loads of the tiny parameter vectors.
    float r[N_QUBITS], k[N_QUBITS - 1];
    #pragma unroll
    for (int i = 0; i < N_QUBITS; i++) r[i] = __ldg(&rot[i]);
    #pragma unroll
    for (int i = 0; i < N_QUBITS - 1; i++)
        k[i] = 0.5f - 0.5f * __cosf(__ldg(&ent[i]));   // sin^2(e/2)

    float x[N_QUBITS];
    #pragma unroll
    for (int i = 0; i < 5; i++) { x[2*i] = v[i].x; x[2*i+1] = v[i].y; }

    // All 10 cos are independent (pipelined MUFU); carry chain is 2 FMA/step.
    float c[N_QUBITS];
    #pragma unroll
    for (int i = 0; i < N_QUBITS; i++) c[i] = __cosf(x[i] + r[i]);

    float e[N_QUBITS];
    float carry = 1.0f;
    #pragma unroll
    for (int i = 0; i < N_QUBITS; i++) {
        float ev = c[i] * carry;
        e[i] = ev;
        if (i < N_QUBITS - 1) carry = 1.0f - k[i] * (1.0f - ev);
    }

    float2* dst = out2 + t * 5;
    #pragma unroll
    for (int i = 0; i < 5; i++) {
        float2 o; o.x = e[2*i]; o.y = e[2*i+1];
        dst[i] = o;
    }
}

extern "C" void kernel_launch(void* const* d_in, const int* in_sizes, int n_in,
                              void* d_out, int out_size) {
    const float* inputs = (const float*)d_in[0];  // (16, 1024, 10) fp32
    const float* rot    = (const float*)d_in[1];  // (10,)
    const float* ent    = (const float*)d_in[2];  // (9,)
    float* out = (float*)d_out;

    int total_elems = in_sizes[0];                 // 163840
    int T = total_elems / N_QUBITS;                // 16384 samples
    int blocks = T / TPB;                          // 128, exact

    qsa_closed_form_kernel<<<blocks, TPB>>>(
        reinterpret_cast<const float2*>(inputs), rot, ent,
        reinterpret_cast<float2*>(out));
}